// round 2
// baseline (speedup 1.0000x reference)
#include <cuda_runtime.h>
#include <cuda_bf16.h>
#include <cstdio>

// Problem constants
#define B 4
#define H 128
#define W 128
#define BINS 64
#define KK 26            // 25 neighbors + current
#define KS 5

// Tiling
#define TH 8             // tile height (output rows per CTA)
#define TW 32            // tile width  (output cols per CTA)
#define PH (TH + 4)      // 12 padded rows (halo 2)
#define PW (TW + 4)      // 36 padded cols
#define NPIXPAD (PH * PW)  // 432 staged pixels
#define PS 433           // pixel stride in s_ref (odd -> decent bank spread on stores)
#define AP 257           // pixel stride in s_attn (odd)
#define THREADS 256

#define SREF_FLOATS (BINS * PS)          // 27712
#define SATTN_FLOATS (KK * AP)           // 6682
#define SMEM_BYTES ((SREF_FLOATS + SATTN_FLOATS) * 4)  // 137576 B

__global__ __launch_bounds__(THREADS, 1)
void agg_kernel(const float* __restrict__ attn,
                const float* __restrict__ refv,
                const float* __restrict__ curv,
                float* __restrict__ out) {
    extern __shared__ float smem[];
    float* s_ref  = smem;                 // [bin][pixel]  bin*PS + pix
    float* s_attn = smem + SREF_FLOATS;   // [k][pixel]    k*AP + pix (pix = r*TW+c)

    const int tid = threadIdx.x;
    const int bidx = blockIdx.x;          // 256 blocks: 4 wt x 16 ht x 4 batch
    const int tw = bidx & 3;
    const int th = (bidx >> 2) & 15;
    const int b  = bidx >> 6;
    const int h0 = th * TH;
    const int w0 = tw * TW;

    const float* refb = refv + (size_t)b * H * W * BINS;

    // ---------- Stage ref_value tile+halo, transposed [bin][pixel] ----------
    // 432 pixels * 16 float4 = 6912 float4 slots; 27 iters per thread.
    #pragma unroll 1
    for (int idx = tid; idx < NPIXPAD * 16; idx += THREADS) {
        int pix = idx >> 4;
        int c4  = (idx & 15) << 2;
        int lr  = pix / PW;
        int lc  = pix - lr * PW;
        int gh  = h0 + lr - 2;
        int gw  = w0 + lc - 2;
        float4 v = make_float4(0.f, 0.f, 0.f, 0.f);
        if ((unsigned)gh < (unsigned)H && (unsigned)gw < (unsigned)W) {
            v = *reinterpret_cast<const float4*>(refb + ((gh * W + gw) * BINS + c4));
        }
        s_ref[(c4 + 0) * PS + pix] = v.x;
        s_ref[(c4 + 1) * PS + pix] = v.y;
        s_ref[(c4 + 2) * PS + pix] = v.z;
        s_ref[(c4 + 3) * PS + pix] = v.w;
    }

    // ---------- Stage attn tile, transposed [k][pixel] ----------
    // 8 rows * 32 cols * 26 = 6656 floats; 26 iters per thread, coalesced reads.
    #pragma unroll 1
    for (int idx = tid; idx < TH * TW * KK; idx += THREADS) {
        int r   = idx / (TW * KK);
        int rem = idx - r * (TW * KK);
        int w   = rem / KK;
        int k   = rem - w * KK;
        float a = attn[(((b * H + h0 + r) * W) + (w0 + w)) * KK + k];
        s_attn[k * AP + r * TW + w] = a;
    }

    __syncthreads();

    // ---------- Compute: each thread = 4 vertical pixels x 16 bins ----------
    const int c  = tid & 31;          // column within tile 0..31
    const int rg = (tid >> 5) & 1;    // row group 0..1
    const int bg = tid >> 6;          // bin group 0..3
    const int r0 = rg * 4;            // first output row of this thread
    const int bb = bg * 16;           // first bin of this thread

    float acc[4][16];
    #pragma unroll
    for (int rr = 0; rr < 4; ++rr)
        #pragma unroll
        for (int i = 0; i < 16; ++i) acc[rr][i] = 0.f;

    // smem row for output row (r0+rr), vertical offset di in 0..4 is (r0+rr+di).
    // Loop absolute staged row ar = rr + di in 0..7; each loaded vector feeds up
    // to 4 output rows (2.5x reuse of smem reads).
    #pragma unroll
    for (int ar = 0; ar < 8; ++ar) {
        #pragma unroll
        for (int dj = 0; dj < 5; ++dj) {
            const int sp = (r0 + ar) * PW + (c + dj);
            float v[16];
            #pragma unroll
            for (int i = 0; i < 16; ++i) v[i] = s_ref[(bb + i) * PS + sp];
            #pragma unroll
            for (int rr = 0; rr < 4; ++rr) {
                const int di = ar - rr;
                if (di < 0 || di > 4) continue;   // compile-time pruned
                const float a = s_attn[(di * KS + dj) * AP + (r0 + rr) * TW + c];
                #pragma unroll
                for (int i = 0; i < 16; ++i)
                    acc[rr][i] = fmaf(a, v[i], acc[rr][i]);
            }
        }
    }

    __syncthreads();   // everyone done reading s_ref before we overwrite it

    // ---------- Transpose accumulators back through s_ref [bin][outpix] ----------
    #pragma unroll
    for (int rr = 0; rr < 4; ++rr) {
        const int pix = (r0 + rr) * TW + c;   // 0..255
        #pragma unroll
        for (int i = 0; i < 16; ++i)
            s_ref[(bb + i) * PS + pix] = acc[rr][i];
    }

    __syncthreads();

    // ---------- Epilogue: += attn[25]*current, coalesced float4 store ----------
    // 8*32*64 = 16384 floats = 4096 float4; 16 iters per thread.
    const float* curb = curv + (size_t)b * H * W * BINS;
    float* outb = out + (size_t)b * H * W * BINS;
    #pragma unroll 1
    for (int it = tid; it < TH * TW * 16; it += THREADS) {
        int pix = it >> 4;
        int c4  = (it & 15) << 2;
        int r   = pix >> 5;
        int cw  = pix & 31;
        int gaddr = ((h0 + r) * W + (w0 + cw)) * BINS + c4;
        float4 cv = *reinterpret_cast<const float4*>(curb + gaddr);
        float a25 = s_attn[25 * AP + pix];
        float4 o;
        o.x = s_ref[(c4 + 0) * PS + pix] + a25 * cv.x;
        o.y = s_ref[(c4 + 1) * PS + pix] + a25 * cv.y;
        o.z = s_ref[(c4 + 2) * PS + pix] + a25 * cv.z;
        o.w = s_ref[(c4 + 3) * PS + pix] + a25 * cv.w;
        *reinterpret_cast<float4*>(outb + gaddr) = o;
    }
}

extern "C" void kernel_launch(void* const* d_in, const int* in_sizes, int n_in,
                              void* d_out, int out_size) {
    const float* attn = (const float*)d_in[0];   // [4,128,128,26]
    const float* refv = (const float*)d_in[1];   // [4,128,128,64]
    const float* curv = (const float*)d_in[2];   // [4,128,128,64]
    float* out = (float*)d_out;                  // [4,128,128,64]

    // Opt in to >48KB dynamic smem (idempotent, host-side, not a stream op).
    cudaFuncSetAttribute(agg_kernel, cudaFuncAttributeMaxDynamicSharedMemorySize,
                         SMEM_BYTES);

    const int nblocks = B * (H / TH) * (W / TW);   // 4*16*4 = 256
    agg_kernel<<<nblocks, THREADS, SMEM_BYTES>>>(attn, refv, curv, out);
}

// round 3
// speedup vs baseline: 2.0626x; 2.0626x over previous
#include <cuda_runtime.h>
#include <cstdint>

// Problem constants
#define B 4
#define H 128
#define W 128
#define BINS 64
#define KK 26            // 25 neighbors + current
#define KS 5

// Tiling: 4 x 32 output pixels per CTA, halo 2 -> 8 x 36 staged pixels
#define TH 4
#define TW 32
#define PH (TH + 4)      // 8
#define PW (TW + 4)      // 36
#define NPIX (PH * PW)   // 288 staged pixels
#define AS 133           // attn pixel-stride (5k+pix mod 32 conflict-free on stage)
#define THREADS 256

#define SREF_FLOATS (NPIX * BINS)      // 18432 (natural [pixel][bin] layout)
#define SATTN_FLOATS (KK * AS)         // 3458
#define SMEM_BYTES ((SREF_FLOATS + SATTN_FLOATS) * 4)   // 87560 B -> 2 CTAs/SM

__device__ __forceinline__ void cp_async16(uint32_t dst, const void* src, int src_bytes) {
    asm volatile("cp.async.cg.shared.global [%0], [%1], 16, %2;\n"
                 :: "r"(dst), "l"(src), "r"(src_bytes) : "memory");
}

__global__ __launch_bounds__(THREADS, 2)
void agg_kernel(const float* __restrict__ attn,
                const float* __restrict__ refv,
                const float* __restrict__ curv,
                float* __restrict__ out) {
    extern __shared__ float smem[];
    float* s_ref  = smem;                 // [pix][bin], pix = lr*PW + lc
    float* s_attn = smem + SREF_FLOATS;   // [k][pix],  pix = r*TW + c

    const int tid  = threadIdx.x;
    const int bidx = blockIdx.x;          // 512 blocks: 4 tw x 32 th x 4 batch
    const int tw = bidx & 3;
    const int th = (bidx >> 2) & 31;
    const int b  = bidx >> 7;
    const int h0 = th * TH;
    const int w0 = tw * TW;

    const float* refb = refv + (size_t)b * H * W * BINS;

    // ---------- Stage ref tile+halo via cp.async (natural layout) ----------
    // 288 pixels * 16 float4 = 4608 chunks = 18 per thread, fully coalesced.
    const uint32_t s_ref_b = (uint32_t)__cvta_generic_to_shared(s_ref);
    #pragma unroll
    for (int i = 0; i < (NPIX * 16) / THREADS; ++i) {
        int idx = tid + i * THREADS;
        int g   = idx & 15;              // float4 group within pixel
        int pix = idx >> 4;
        int lr  = pix / PW;
        int lc  = pix - lr * PW;
        int gh  = h0 + lr - 2;
        int gw  = w0 + lc - 2;
        bool ok = ((unsigned)gh < (unsigned)H) && ((unsigned)gw < (unsigned)W);
        const float* src = refb + (((ok ? gh : 0) * W + (ok ? gw : 0)) * BINS + g * 4);
        uint32_t dst = s_ref_b + (uint32_t)((pix * BINS + g * 4) * 4);
        cp_async16(dst, src, ok ? 16 : 0);   // zero-fill halo
    }
    asm volatile("cp.async.commit_group;\n" ::: "memory");

    // ---------- Stage attn tile, transposed [k][pix] (coalesced reads) ----------
    #pragma unroll 1
    for (int idx = tid; idx < TH * TW * KK; idx += THREADS) {
        int pix = idx / KK;
        int k   = idx - pix * KK;
        int r   = pix >> 5;
        int c   = pix & 31;
        float a = attn[(((b * H + h0 + r) * W) + (w0 + c)) * KK + k];
        s_attn[k * AS + pix] = a;
    }

    asm volatile("cp.async.wait_group 0;\n" ::: "memory");
    __syncthreads();

    // ---------- Compute: thread = 8 adjacent pixels (one row) x 4 bins ----------
    const int bg = tid & 15;             // float4 group 0..15 (bins bg*4..bg*4+3)
    const int pg = tid >> 4;             // 0..15
    const int r  = pg >> 2;              // output row 0..3
    const int c0 = (pg & 3) * 8;         // first output col of this thread

    float4 acc[8];
    #pragma unroll
    for (int p = 0; p < 8; ++p) acc[p] = make_float4(0.f, 0.f, 0.f, 0.f);

    #pragma unroll
    for (int di = 0; di < 5; ++di) {
        // padded row for output row r, vertical tap di: (r+di); leftmost col c0
        const float* vrow = s_ref + ((r + di) * PW + c0) * BINS + bg * 4;
        float4 v[12];                    // 12-wide sliding window (8 outputs + 4 halo)
        #pragma unroll
        for (int j = 0; j < 12; ++j)
            v[j] = *reinterpret_cast<const float4*>(vrow + j * BINS);
        #pragma unroll
        for (int dj = 0; dj < 5; ++dj) {
            const float* arow = s_attn + (di * KS + dj) * AS + r * TW + c0;
            #pragma unroll
            for (int p = 0; p < 8; ++p) {
                float a = arow[p];       // warp broadcast (2 addrs/warp)
                acc[p].x = fmaf(a, v[p + dj].x, acc[p].x);
                acc[p].y = fmaf(a, v[p + dj].y, acc[p].y);
                acc[p].z = fmaf(a, v[p + dj].z, acc[p].z);
                acc[p].w = fmaf(a, v[p + dj].w, acc[p].w);
            }
        }
    }

    // ---------- Epilogue: += attn[25]*current, direct coalesced float4 ----------
    const float* curb = curv + (size_t)b * H * W * BINS;
    float*       outb = out  + (size_t)b * H * W * BINS;
    const float* a25  = s_attn + 25 * AS + r * TW + c0;
    #pragma unroll
    for (int p = 0; p < 8; ++p) {
        int gaddr = ((h0 + r) * W + (w0 + c0 + p)) * BINS + bg * 4;
        float4 cv = *reinterpret_cast<const float4*>(curb + gaddr);
        float a = a25[p];
        float4 o;
        o.x = fmaf(a, cv.x, acc[p].x);
        o.y = fmaf(a, cv.y, acc[p].y);
        o.z = fmaf(a, cv.z, acc[p].z);
        o.w = fmaf(a, cv.w, acc[p].w);
        *reinterpret_cast<float4*>(outb + gaddr) = o;
    }
}

extern "C" void kernel_launch(void* const* d_in, const int* in_sizes, int n_in,
                              void* d_out, int out_size) {
    const float* attn = (const float*)d_in[0];   // [4,128,128,26]
    const float* refv = (const float*)d_in[1];   // [4,128,128,64]
    const float* curv = (const float*)d_in[2];   // [4,128,128,64]
    float* out = (float*)d_out;                  // [4,128,128,64]

    cudaFuncSetAttribute(agg_kernel, cudaFuncAttributeMaxDynamicSharedMemorySize,
                         SMEM_BYTES);

    const int nblocks = B * (H / TH) * (W / TW);   // 4*32*4 = 512
    agg_kernel<<<nblocks, THREADS, SMEM_BYTES>>>(attn, refv, curv, out);
}